// round 6
// baseline (speedup 1.0000x reference)
#include <cuda_runtime.h>
#include <cstdint>

// Problem dims (fixed by setup_inputs)
#define C_DIM   4096
#define K_DIM   4096
#define M_TOT   8192            // B*X = 2*4096
#define NBLK    128             // C / 32

// GEMM tiling
#define BM      128
#define BN      256
#define BK      32
#define STAGES  3
#define KITERS  (C_DIM / BK)    // 128

// Per-stage smem tiles (swizzled row-major, 128B rows)
#define A_STAGE_BYTES   (BM * BK * 4)              // 16384
#define B_STAGE_BYTES   (BN * BK * 4)              // 32768
#define STAGE_BYTES     (A_STAGE_BYTES + B_STAGE_BYTES)
#define SMEM_TOTAL      (STAGES * STAGE_BYTES)     // 147456

// Dequantized, tf32-rounded scratch. Static device globals (allocation-free).
__device__ float g_A[(size_t)M_TOT * C_DIM];   // 128 MiB
__device__ float g_B[(size_t)K_DIM * C_DIM];   //  64 MiB

// ---------------------------------------------------------------------------
// Helpers (base-ISA PTX only: sm_80-era. No 'a'-suffix instructions.)
// ---------------------------------------------------------------------------

__device__ __forceinline__ float tf32_rna(float x) {
    uint32_t u;
    asm("cvt.rna.tf32.f32 %0, %1;" : "=r"(u) : "f"(x));
    return __uint_as_float(u);
}

__device__ __forceinline__ void cp_async16(uint32_t smem_addr, const void* gptr) {
    asm volatile("cp.async.cg.shared.global [%0], [%1], 16;"
                 :: "r"(smem_addr), "l"(gptr) : "memory");
}
__device__ __forceinline__ void cp_commit() {
    asm volatile("cp.async.commit_group;" ::: "memory");
}
template <int N>
__device__ __forceinline__ void cp_wait() {
    asm volatile("cp.async.wait_group %0;" :: "n"(N) : "memory");
}

// m16n8k8 tf32 MMA, fp32 accumulate (base PTX, sm_80+)
__device__ __forceinline__ void mma_16n8k8(float* d, const float* a, const float* b) {
    asm volatile(
        "mma.sync.aligned.m16n8k8.row.col.f32.tf32.tf32.f32 "
        "{%0,%1,%2,%3}, {%4,%5,%6,%7}, {%8,%9}, {%0,%1,%2,%3};"
        : "+f"(d[0]), "+f"(d[1]), "+f"(d[2]), "+f"(d[3])
        : "r"(__float_as_uint(a[0])), "r"(__float_as_uint(a[1])),
          "r"(__float_as_uint(a[2])), "r"(__float_as_uint(a[3])),
          "r"(__float_as_uint(b[0])), "r"(__float_as_uint(b[1])));
}

// Swizzled byte offset inside a tile: row-major, 128B rows, chunk-XOR swizzle.
// byte(row, colf) = row*128 + ((colf*4) ^ ((row&7)<<4))
__device__ __forceinline__ uint32_t sw_off(uint32_t row, uint32_t colf) {
    return row * 128u + ((colf * 4u) ^ ((row & 7u) << 4));
}

// ---------------------------------------------------------------------------
// Dequant pre-pass: dst = round_rna_tf32(src * scale[block]).
// src rows are 4096 floats; scale blocks of 32 -> 8 float4 per block.
// ---------------------------------------------------------------------------
__global__ void dequant_kernel(const float* __restrict__ src,
                               const float* __restrict__ scale,
                               float* __restrict__ dst, int n4) {
    int i = blockIdx.x * blockDim.x + threadIdx.x;
    if (i >= n4) return;
    int row = i >> 10;          // 1024 float4 per row
    int c4  = i & 1023;
    float s = __ldg(&scale[row * NBLK + (c4 >> 3)]);
    float4 v = reinterpret_cast<const float4*>(src)[i];
    float4 o;
    o.x = tf32_rna(v.x * s);
    o.y = tf32_rna(v.y * s);
    o.z = tf32_rna(v.z * s);
    o.w = tf32_rna(v.w * s);
    reinterpret_cast<float4*>(dst)[i] = o;
}

// ---------------------------------------------------------------------------
// mma.sync tf32 GEMM: out[m,n] = sum_c A[m,c]*B[n,c] + bias[n]
// Grid (K_DIM/BN, M_TOT/BM) = (16, 64). 256 threads = 8 warps (2 m x 4 n),
// warp tile 64x64. cp.async 3-stage pipeline, XOR-swizzled smem.
// ---------------------------------------------------------------------------
__global__ void __launch_bounds__(256, 1)
gemm_tf32_kernel(const float* __restrict__ gA,
                 const float* __restrict__ gB,
                 const float* __restrict__ bias,
                 float* __restrict__ out) {
    extern __shared__ char smem[];
    const uint32_t smem_u32 = (uint32_t)__cvta_generic_to_shared(smem);

    const int tid   = threadIdx.x;
    const int lane  = tid & 31;
    const int wid   = tid >> 5;
    const int wm0   = (wid & 1) * 64;     // warp row offset in tile
    const int wn0   = (wid >> 1) * 64;    // warp col offset in tile

    const int tileN = blockIdx.x;
    const int tileM = blockIdx.y;
    const size_t rowA0 = (size_t)tileM * BM;
    const size_t rowB0 = (size_t)tileN * BN;

    // -------- cp.async tile loader (per stage) --------
    // A: 128 rows x 8 16B-chunks = 1024 chunks -> 4 per thread
    // B: 256 rows x 8 chunks = 2048 -> 8 per thread
    auto load_stage = [&](int s, int kit) {
        const uint32_t aBase = smem_u32 + s * STAGE_BYTES;
        const uint32_t bBase = aBase + A_STAGE_BYTES;
        const size_t kcol = (size_t)kit * BK;
        #pragma unroll
        for (int t = 0; t < 4; t++) {
            int idx = tid + t * 256;
            int r = idx >> 3, c = idx & 7;
            const float* src = gA + (rowA0 + r) * C_DIM + kcol + c * 4;
            cp_async16(aBase + r * 128 + ((c ^ (r & 7)) << 4), src);
        }
        #pragma unroll
        for (int t = 0; t < 8; t++) {
            int idx = tid + t * 256;
            int r = idx >> 3, c = idx & 7;
            const float* src = gB + (rowB0 + r) * C_DIM + kcol + c * 4;
            cp_async16(bBase + r * 128 + ((c ^ (r & 7)) << 4), src);
        }
        cp_commit();
    };

    // -------- accumulators --------
    float acc[4][8][4];
    #pragma unroll
    for (int i = 0; i < 4; i++)
        #pragma unroll
        for (int j = 0; j < 8; j++)
            #pragma unroll
            for (int r = 0; r < 4; r++) acc[i][j][r] = 0.0f;

    // -------- prologue --------
    load_stage(0, 0);
    load_stage(1, 1);

    const int lr = lane >> 2;    // 0..7
    const int lc = lane & 3;     // 0..3

    // -------- mainloop --------
    for (int it = 0; it < KITERS; it++) {
        cp_wait<1>();
        __syncthreads();

        if (it + 2 < KITERS) load_stage((it + 2) % STAGES, it + 2);
        else                 cp_commit();   // keep group count uniform

        const int s = it % STAGES;
        const char* aTile = smem + s * STAGE_BYTES;
        const char* bTile = aTile + A_STAGE_BYTES;

        #pragma unroll
        for (int kk = 0; kk < 4; kk++) {
            const int k0 = kk * 8;
            float af[4][4], bf[8][2];
            #pragma unroll
            for (int i = 0; i < 4; i++) {
                const uint32_t r0 = wm0 + i * 16 + lr;
                af[i][0] = *(const float*)(aTile + sw_off(r0,     k0 + lc));
                af[i][1] = *(const float*)(aTile + sw_off(r0 + 8, k0 + lc));
                af[i][2] = *(const float*)(aTile + sw_off(r0,     k0 + lc + 4));
                af[i][3] = *(const float*)(aTile + sw_off(r0 + 8, k0 + lc + 4));
            }
            #pragma unroll
            for (int j = 0; j < 8; j++) {
                const uint32_t rn = wn0 + j * 8 + lr;
                bf[j][0] = *(const float*)(bTile + sw_off(rn, k0 + lc));
                bf[j][1] = *(const float*)(bTile + sw_off(rn, k0 + lc + 4));
            }
            #pragma unroll
            for (int i = 0; i < 4; i++)
                #pragma unroll
                for (int j = 0; j < 8; j++)
                    mma_16n8k8(acc[i][j], af[i], bf[j]);
        }
        __syncthreads();
    }

    // -------- epilogue: bias add + store --------
    // D frag: c0 at (row=lr, col=lc*2), c1 col+1, c2/c3 at row+8.
    #pragma unroll
    for (int i = 0; i < 4; i++) {
        const size_t r0 = rowA0 + wm0 + i * 16 + lr;
        #pragma unroll
        for (int j = 0; j < 8; j++) {
            const size_t col = rowB0 + wn0 + j * 8 + lc * 2;
            const float2 b2 = *reinterpret_cast<const float2*>(bias + col);
            float2 o0, o1;
            o0.x = acc[i][j][0] + b2.x;
            o0.y = acc[i][j][1] + b2.y;
            o1.x = acc[i][j][2] + b2.x;
            o1.y = acc[i][j][3] + b2.y;
            *reinterpret_cast<float2*>(out + r0 * K_DIM + col)       = o0;
            *reinterpret_cast<float2*>(out + (r0 + 8) * K_DIM + col) = o1;
        }
    }
}

// ---------------------------------------------------------------------------
// Host
// ---------------------------------------------------------------------------
extern "C" void kernel_launch(void* const* d_in, const int* in_sizes, int n_in,
                              void* d_out, int out_size) {
    const float* x    = (const float*)d_in[0];   // (2, 4096, 4096)
    const float* w    = (const float*)d_in[1];   // (4096, 4096)
    const float* bias = (const float*)d_in[2];   // (4096,)
    const float* sx   = (const float*)d_in[3];   // (2, 4096, 128)
    const float* sw   = (const float*)d_in[4];   // (4096, 128)

    void* pA = nullptr;
    void* pB = nullptr;
    cudaGetSymbolAddress(&pA, g_A);
    cudaGetSymbolAddress(&pB, g_B);

    // Dequant pre-passes (tf32-RNA rounded)
    int n4A = M_TOT * C_DIM / 4;
    int n4B = K_DIM * C_DIM / 4;
    dequant_kernel<<<n4A / 256, 256>>>(x, sx, (float*)pA, n4A);
    dequant_kernel<<<n4B / 256, 256>>>(w, sw, (float*)pB, n4B);

    // GEMM
    cudaFuncSetAttribute(gemm_tf32_kernel,
                         cudaFuncAttributeMaxDynamicSharedMemorySize, SMEM_TOTAL);
    dim3 grid(K_DIM / BN, M_TOT / BM);   // (16, 64)
    gemm_tf32_kernel<<<grid, 256, SMEM_TOTAL>>>((const float*)pA, (const float*)pB,
                                                bias, (float*)d_out);
}